// round 1
// baseline (speedup 1.0000x reference)
#include <cuda_runtime.h>
#include <cstddef>

#define NN 50000
#define NE 1600000
#define HID 64

// ---------------- device scratch (no runtime allocation allowed) ----------------
__device__ float g_insum[(size_t)NN * HID];
__device__ float g_A[(size_t)NN * HID];
__device__ float g_B[(size_t)NN * HID];
__device__ float g_nodemsg[(size_t)NN * HID];
__device__ int   g_count[NN];
__device__ int   g_start[NN + 1];
__device__ int   g_cursor[NN];
__device__ int   g_eid[NE];

// ---------------- CSR build ----------------
__global__ void k_zero_counts() {
    int i = blockIdx.x * blockDim.x + threadIdx.x;
    if (i < NN) g_count[i] = 0;
}

__global__ void k_count(const int* __restrict__ ei) {
    int i = blockIdx.x * blockDim.x + threadIdx.x;
    if (i < NE) atomicAdd(&g_count[ei[i]], 1);
}

__global__ void k_scan() {
    // single block, 1024 threads: chunked exclusive scan over g_count
    __shared__ int s[1024];
    const int t = threadIdx.x;
    const int chunk = (NN + 1023) / 1024;  // 49
    int b = t * chunk;
    int e = b + chunk; if (e > NN) e = NN;
    int sum = 0;
    for (int i = b; i < e && i < NN; i++) sum += g_count[i];
    s[t] = sum;
    __syncthreads();
    for (int off = 1; off < 1024; off <<= 1) {
        int v = (t >= off) ? s[t - off] : 0;
        __syncthreads();
        s[t] += v;
        __syncthreads();
    }
    int run = (t == 0) ? 0 : s[t - 1];
    for (int i = b; i < e && i < NN; i++) {
        int c = g_count[i];
        g_start[i] = run;
        g_cursor[i] = run;
        run += c;
    }
    if (t == 1023) g_start[NN] = run;
}

__global__ void k_fill(const int* __restrict__ ei) {
    int i = blockIdx.x * blockDim.x + threadIdx.x;
    if (i < NE) {
        int p = atomicAdd(&g_cursor[ei[i]], 1);
        g_eid[p] = i;
    }
}

// ---------------- segment sums (gather, no float atomics) ----------------
__global__ void k_insum(const float* __restrict__ eh) {
    int gw = (blockIdx.x * blockDim.x + threadIdx.x) >> 5;
    int lane = threadIdx.x & 31;
    if (gw >= NN) return;
    int s = g_start[gw], e = g_start[gw + 1];
    float2 acc = make_float2(0.f, 0.f);
    for (int j = s; j < e; j++) {
        int eid = g_eid[j];
        float2 v = *((const float2*)(eh + (size_t)eid * HID) + lane);
        acc.x += v.x; acc.y += v.y;
    }
    *((float2*)(g_insum + (size_t)gw * HID) + lane) = acc;
}

// node_msg[n] = sum over edges with col==n  ==  sum over j in rowCSR[n] of messages[eid^1]
__global__ void k_nodemsg(const float* __restrict__ msg) {
    int gw = (blockIdx.x * blockDim.x + threadIdx.x) >> 5;
    int lane = threadIdx.x & 31;
    if (gw >= NN) return;
    int s = g_start[gw], e = g_start[gw + 1];
    float2 acc = make_float2(0.f, 0.f);
    for (int j = s; j < e; j++) {
        int eid = g_eid[j] ^ 1;
        float2 v = *((const float2*)(msg + (size_t)eid * HID) + lane);
        acc.x += v.x; acc.y += v.y;
    }
    *((float2*)(g_nodemsg + (size_t)gw * HID) + lane) = acc;
}

// ---------------- small node GEMMs: A = x@W1^T, B = insum@W2^T + b ----------------
// 64-node x 64-out tile, 128 threads, thread tile 4n x 8o
__global__ void __launch_bounds__(128) k_AB(const float* __restrict__ x,
                                            const float* __restrict__ Wm,
                                            const float* __restrict__ bm) {
    __shared__ float s_in[64][68];
    __shared__ float s_W[64][68];
    const int t = threadIdx.x;
    const int base = blockIdx.x * 64;
    const int e0 = (t & 15) * 4;
    const int o0 = (t >> 4) * 8;
    float acc[4][8];

    for (int pass = 0; pass < 2; pass++) {
        const int koff = pass * 64;  // W1 vs W2
        // W tile: s_W[k][o] = Wm[o*128 + koff + k]
        for (int idx = t; idx < 4096; idx += 128) {
            int k = idx & 63, o = idx >> 6;
            s_W[k][o] = Wm[o * 128 + koff + k];
        }
        // input tile transposed
        const float* src = (pass == 0) ? x : g_insum;
        for (int fi = t; fi < 1024; fi += 128) {
            int nl = fi >> 4, kq = fi & 15;
            int n = base + nl;
            float4 v = make_float4(0.f, 0.f, 0.f, 0.f);
            if (n < NN) v = *(const float4*)&src[(size_t)n * HID + kq * 4];
            s_in[kq * 4 + 0][nl] = v.x;
            s_in[kq * 4 + 1][nl] = v.y;
            s_in[kq * 4 + 2][nl] = v.z;
            s_in[kq * 4 + 3][nl] = v.w;
        }
        __syncthreads();

#pragma unroll
        for (int i = 0; i < 4; i++)
#pragma unroll
            for (int j = 0; j < 8; j++) acc[i][j] = 0.f;

        for (int k = 0; k < 64; k++) {
            float4 a = *(float4*)&s_in[k][e0];
            float4 b0 = *(float4*)&s_W[k][o0];
            float4 b1 = *(float4*)&s_W[k][o0 + 4];
            float av[4] = {a.x, a.y, a.z, a.w};
            float bv[8] = {b0.x, b0.y, b0.z, b0.w, b1.x, b1.y, b1.z, b1.w};
#pragma unroll
            for (int i = 0; i < 4; i++)
#pragma unroll
                for (int j = 0; j < 8; j++) acc[i][j] += av[i] * bv[j];
        }

        float bb[8];
        if (pass == 1) {
#pragma unroll
            for (int j = 0; j < 8; j++) bb[j] = bm[o0 + j];
        } else {
#pragma unroll
            for (int j = 0; j < 8; j++) bb[j] = 0.f;
        }
        float* dst = (pass == 0) ? g_A : g_B;
#pragma unroll
        for (int i = 0; i < 4; i++) {
            int n = base + e0 + i;
            if (n < NN) {
                float4 r0 = make_float4(acc[i][0] + bb[0], acc[i][1] + bb[1],
                                        acc[i][2] + bb[2], acc[i][3] + bb[3]);
                float4 r1 = make_float4(acc[i][4] + bb[4], acc[i][5] + bb[5],
                                        acc[i][6] + bb[6], acc[i][7] + bb[7]);
                *(float4*)&dst[(size_t)n * HID + o0] = r0;
                *(float4*)&dst[(size_t)n * HID + o0 + 4] = r1;
            }
        }
        __syncthreads();
    }
}

// ---------------- heavy kernel: Q = eh@W2^T, messages = relu(A[row]+B[col]-Q[rev]) ----------------
__global__ void __launch_bounds__(128) k_msg(const float* __restrict__ eh,
                                             const int* __restrict__ ei,
                                             const float* __restrict__ Wm,
                                             float* __restrict__ msg) {
    __shared__ float s_eh[64][68];
    __shared__ float s_W[64][68];
    __shared__ int s_row[64];
    __shared__ int s_col[64];
    const int t = threadIdx.x;
    const int base = blockIdx.x * 64;

    // W2 tile
    for (int idx = t; idx < 4096; idx += 128) {
        int k = idx & 63, o = idx >> 6;
        s_W[k][o] = Wm[o * 128 + 64 + k];
    }
    // eh tile, transposed [k][e]
    for (int fi = t; fi < 1024; fi += 128) {
        int el = fi >> 4, kq = fi & 15;
        float4 v = *(const float4*)&eh[(size_t)(base + el) * HID + kq * 4];
        s_eh[kq * 4 + 0][el] = v.x;
        s_eh[kq * 4 + 1][el] = v.y;
        s_eh[kq * 4 + 2][el] = v.z;
        s_eh[kq * 4 + 3][el] = v.w;
    }
    if (t < 64) {
        s_row[t] = ei[base + t];
        s_col[t] = ei[NE + base + t];
    }
    __syncthreads();

    const int e0 = (t & 15) * 4;
    const int o0 = (t >> 4) * 8;
    float acc[4][8];
#pragma unroll
    for (int i = 0; i < 4; i++)
#pragma unroll
        for (int j = 0; j < 8; j++) acc[i][j] = 0.f;

    for (int k = 0; k < 64; k++) {
        float4 a = *(float4*)&s_eh[k][e0];
        float4 b0 = *(float4*)&s_W[k][o0];
        float4 b1 = *(float4*)&s_W[k][o0 + 4];
        float av[4] = {a.x, a.y, a.z, a.w};
        float bv[8] = {b0.x, b0.y, b0.z, b0.w, b1.x, b1.y, b1.z, b1.w};
#pragma unroll
        for (int i = 0; i < 4; i++)
#pragma unroll
            for (int j = 0; j < 8; j++) acc[i][j] += av[i] * bv[j];
    }

    // epilogue: pairs (e0,e0+1),(e0+2,e0+3) are reverse pairs (e0 % 4 == 0, global pairing 2k/2k+1)
#pragma unroll
    for (int i = 0; i < 4; i++) {
        int el = e0 + i;
        size_t ge = (size_t)(base + el);
        int r = s_row[el];
        int c = s_col[el];
        const float* Ar = g_A + (size_t)r * HID + o0;
        const float* Bc = g_B + (size_t)c * HID + o0;
        float4 a0 = *(const float4*)Ar;
        float4 a1 = *(const float4*)(Ar + 4);
        float4 b0 = *(const float4*)Bc;
        float4 b1 = *(const float4*)(Bc + 4);
        int p = i ^ 1;
        float out[8];
        out[0] = a0.x + b0.x - acc[p][0];
        out[1] = a0.y + b0.y - acc[p][1];
        out[2] = a0.z + b0.z - acc[p][2];
        out[3] = a0.w + b0.w - acc[p][3];
        out[4] = a1.x + b1.x - acc[p][4];
        out[5] = a1.y + b1.y - acc[p][5];
        out[6] = a1.z + b1.z - acc[p][6];
        out[7] = a1.w + b1.w - acc[p][7];
#pragma unroll
        for (int j = 0; j < 8; j++) out[j] = out[j] > 0.f ? out[j] : 0.f;
        *(float4*)&msg[ge * HID + o0] = make_float4(out[0], out[1], out[2], out[3]);
        *(float4*)&msg[ge * HID + o0 + 4] = make_float4(out[4], out[5], out[6], out[7]);
    }
}

// ---------------- x_out = relu([x, node_msg] @ Wn^T + bn) ----------------
__global__ void __launch_bounds__(128) k_xout(const float* __restrict__ x,
                                              const float* __restrict__ Wn,
                                              const float* __restrict__ bn,
                                              float* __restrict__ xout) {
    __shared__ float s_in[64][68];
    __shared__ float s_W[64][68];
    const int t = threadIdx.x;
    const int base = blockIdx.x * 64;
    const int e0 = (t & 15) * 4;
    const int o0 = (t >> 4) * 8;
    float acc[4][8];
#pragma unroll
    for (int i = 0; i < 4; i++)
#pragma unroll
        for (int j = 0; j < 8; j++) acc[i][j] = 0.f;

    for (int pass = 0; pass < 2; pass++) {
        const int koff = pass * 64;
        for (int idx = t; idx < 4096; idx += 128) {
            int k = idx & 63, o = idx >> 6;
            s_W[k][o] = Wn[o * 128 + koff + k];
        }
        const float* src = (pass == 0) ? x : g_nodemsg;
        for (int fi = t; fi < 1024; fi += 128) {
            int nl = fi >> 4, kq = fi & 15;
            int n = base + nl;
            float4 v = make_float4(0.f, 0.f, 0.f, 0.f);
            if (n < NN) v = *(const float4*)&src[(size_t)n * HID + kq * 4];
            s_in[kq * 4 + 0][nl] = v.x;
            s_in[kq * 4 + 1][nl] = v.y;
            s_in[kq * 4 + 2][nl] = v.z;
            s_in[kq * 4 + 3][nl] = v.w;
        }
        __syncthreads();
        for (int k = 0; k < 64; k++) {
            float4 a = *(float4*)&s_in[k][e0];
            float4 b0 = *(float4*)&s_W[k][o0];
            float4 b1 = *(float4*)&s_W[k][o0 + 4];
            float av[4] = {a.x, a.y, a.z, a.w};
            float bv[8] = {b0.x, b0.y, b0.z, b0.w, b1.x, b1.y, b1.z, b1.w};
#pragma unroll
            for (int i = 0; i < 4; i++)
#pragma unroll
                for (int j = 0; j < 8; j++) acc[i][j] += av[i] * bv[j];
        }
        __syncthreads();
    }

    float bb[8];
#pragma unroll
    for (int j = 0; j < 8; j++) bb[j] = bn[o0 + j];
#pragma unroll
    for (int i = 0; i < 4; i++) {
        int n = base + e0 + i;
        if (n < NN) {
            float o[8];
#pragma unroll
            for (int j = 0; j < 8; j++) {
                float v = acc[i][j] + bb[j];
                o[j] = v > 0.f ? v : 0.f;
            }
            *(float4*)&xout[(size_t)n * HID + o0] = make_float4(o[0], o[1], o[2], o[3]);
            *(float4*)&xout[(size_t)n * HID + o0 + 4] = make_float4(o[4], o[5], o[6], o[7]);
        }
    }
}

// ---------------- launch ----------------
extern "C" void kernel_launch(void* const* d_in, const int* in_sizes, int n_in,
                              void* d_out, int out_size) {
    const float* x  = (const float*)d_in[0];
    const int*   ei = (const int*)d_in[1];
    const float* eh = (const float*)d_in[2];
    const float* Wm = (const float*)d_in[3];
    const float* bm = (const float*)d_in[4];
    const float* Wn = (const float*)d_in[5];
    const float* bn = (const float*)d_in[6];
    float* xout = (float*)d_out;
    float* msg  = (float*)d_out + (size_t)NN * HID;

    k_zero_counts<<<(NN + 255) / 256, 256>>>();
    k_count<<<(NE + 255) / 256, 256>>>(ei);
    k_scan<<<1, 1024>>>();
    k_fill<<<(NE + 255) / 256, 256>>>(ei);
    k_insum<<<(NN * 32 + 255) / 256, 256>>>(eh);       // one warp per node
    k_AB<<<(NN + 63) / 64, 128>>>(x, Wm, bm);
    k_msg<<<NE / 64, 128>>>(eh, ei, Wm, msg);
    k_nodemsg<<<(NN * 32 + 255) / 256, 256>>>(msg);    // one warp per node
    k_xout<<<(NN + 63) / 64, 128>>>(x, Wn, bn, xout);
}